// round 1
// baseline (speedup 1.0000x reference)
#include <cuda_runtime.h>
#include <cuda_bf16.h>
#include <math.h>
#include <stdint.h>

// ---------------------------------------------------------------------------
// Problem constants (shapes fixed by the dataset)
// ---------------------------------------------------------------------------
#define BATCH   4
#define SEQ     2048
#define DIN     4096
#define DPROJ   512
#define DMEM    512
#define ASSIST  512
#define RUN     1536          // SEQ - ASSIST
#define ROWS    (BATCH*SEQ)   // 8192

// ---------------------------------------------------------------------------
// Device scratch (static allocation is the sanctioned path; no cudaMalloc)
// ---------------------------------------------------------------------------
__device__ float g_Q[(size_t)ROWS*DPROJ];
__device__ float g_K[(size_t)ROWS*DPROJ];
__device__ float g_V[(size_t)ROWS*DPROJ];
__device__ float g_S[(size_t)BATCH*SEQ*SEQ];          // scores / probs (in place)
__device__ float g_feat[(size_t)ROWS*DPROJ];
__device__ float g_Gz[(size_t)BATCH*RUN*DMEM];
__device__ float g_Gr[(size_t)BATCH*RUN*DMEM];
__device__ float g_Gh[(size_t)BATCH*RUN*DMEM];
__device__ float g_h[BATCH*DMEM];
__device__ float g_rh[BATCH*DMEM];
__device__ unsigned g_bar_count = 0;
__device__ volatile unsigned g_bar_sense = 0;

// ---------------------------------------------------------------------------
// Generic tiled SGEMM: C[M,N] = A[M,K] * op(B) (+ bias[N])
//   transB=0: B is [K,N] row-major.  transB=1: B is [N,K] row-major (C=A*B^T)
//   Per-batch strides sA/sB/sC (elements); blockIdx.z = batch.
//   causal=1: skip tiles fully above the diagonal (scores GEMM).
//   Requires M % 128 == 0, N % 64 == 0, K % 16 == 0 (true for all calls).
// ---------------------------------------------------------------------------
__global__ void __launch_bounds__(256) sgemm_kernel(
    const float* __restrict__ A, const float* __restrict__ B,
    const float* __restrict__ bias, float* __restrict__ C,
    int M, int N, int K,
    size_t sA, size_t sB, size_t sC,
    int transB, int causal)
{
    constexpr int BM = 128, BN = 64, BK = 16;
    int bx = blockIdx.x, by = blockIdx.y, bz = blockIdx.z;
    int rowBase = by * BM, colBase = bx * BN;
    if (causal && (rowBase + BM - 1) < colBase) return;   // fully masked tile

    const float* Ab = A + sA * (size_t)bz;
    const float* Bb = B + sB * (size_t)bz;
    float*       Cb = C + sC * (size_t)bz;

    __shared__ float As[BK][BM];
    __shared__ float Bs[BK][BN];

    int tid = threadIdx.x;
    int tx = tid & 15;          // 0..15 -> col group of 4
    int ty = tid >> 4;          // 0..15 -> row group of 8
    int ar = tid >> 1;          // 0..127
    int ak = (tid & 1) * 8;     // 0 or 8
    int ldb = transB ? K : N;

    float acc[8][4];
#pragma unroll
    for (int i = 0; i < 8; i++)
#pragma unroll
        for (int j = 0; j < 4; j++) acc[i][j] = 0.0f;

    for (int k0 = 0; k0 < K; k0 += BK) {
        // load A tile (128x16), transposed into As[k][m]
        const float* ap = Ab + (size_t)(rowBase + ar) * K + k0 + ak;
        float4 a0 = *(const float4*)(ap);
        float4 a1 = *(const float4*)(ap + 4);
        As[ak + 0][ar] = a0.x; As[ak + 1][ar] = a0.y;
        As[ak + 2][ar] = a0.z; As[ak + 3][ar] = a0.w;
        As[ak + 4][ar] = a1.x; As[ak + 5][ar] = a1.y;
        As[ak + 6][ar] = a1.z; As[ak + 7][ar] = a1.w;

        if (!transB) {
            int br = tid >> 4, bc = (tid & 15) * 4;
            float4 bv = *(const float4*)(Bb + (size_t)(k0 + br) * ldb + colBase + bc);
            *(float4*)&Bs[br][bc] = bv;
        } else {
            int bc = tid >> 2, bk = (tid & 3) * 4;
            float4 bv = *(const float4*)(Bb + (size_t)(colBase + bc) * ldb + k0 + bk);
            Bs[bk + 0][bc] = bv.x; Bs[bk + 1][bc] = bv.y;
            Bs[bk + 2][bc] = bv.z; Bs[bk + 3][bc] = bv.w;
        }
        __syncthreads();

#pragma unroll
        for (int kk = 0; kk < BK; kk++) {
            float4 av0 = *(const float4*)&As[kk][ty * 8];
            float4 av1 = *(const float4*)&As[kk][ty * 8 + 4];
            float4 bv0 = *(const float4*)&Bs[kk][tx * 4];
            float a[8] = {av0.x, av0.y, av0.z, av0.w, av1.x, av1.y, av1.z, av1.w};
            float b[4] = {bv0.x, bv0.y, bv0.z, bv0.w};
#pragma unroll
            for (int i = 0; i < 8; i++)
#pragma unroll
                for (int j = 0; j < 4; j++)
                    acc[i][j] = fmaf(a[i], b[j], acc[i][j]);
        }
        __syncthreads();
    }

    float4 bvv = make_float4(0.f, 0.f, 0.f, 0.f);
    if (bias) bvv = *(const float4*)(bias + colBase + tx * 4);
#pragma unroll
    for (int i = 0; i < 8; i++) {
        size_t row = (size_t)(rowBase + ty * 8 + i);
        float4 o = make_float4(acc[i][0] + bvv.x, acc[i][1] + bvv.y,
                               acc[i][2] + bvv.z, acc[i][3] + bvv.w);
        *(float4*)(Cb + row * N + colBase + tx * 4) = o;
    }
}

// ---------------------------------------------------------------------------
// Causal row softmax (in place on g_S). grid=(SEQ, BATCH), 256 threads.
// Matches reference: scores/scale, mask with -1e9 (=> exact zeros in fp32).
// ---------------------------------------------------------------------------
__global__ void softmax_causal_kernel()
{
    int r = blockIdx.x, b = blockIdx.y;
    float* row = g_S + ((size_t)b * SEQ + r) * SEQ;
    int len = r + 1;
    int tid = threadIdx.x;
    __shared__ float red[256];
    const float inv = rsqrtf(512.0f);   // 1e-6 underflows in fp32 anyway

    float m = -3.4e38f;
    for (int i = tid; i < len; i += 256) m = fmaxf(m, row[i]);
    red[tid] = m; __syncthreads();
    for (int s = 128; s; s >>= 1) { if (tid < s) red[tid] = fmaxf(red[tid], red[tid + s]); __syncthreads(); }
    m = red[0] * inv;
    __syncthreads();

    float ssum = 0.0f;
    for (int i = tid; i < len; i += 256) ssum += expf(row[i] * inv - m);
    red[tid] = ssum; __syncthreads();
    for (int s = 128; s; s >>= 1) { if (tid < s) red[tid] += red[tid + s]; __syncthreads(); }
    float denom = 1.0f / red[0];
    __syncthreads();

    for (int i = tid; i < SEQ; i += 256)
        row[i] = (i < len) ? expf(row[i] * inv - m) * denom : 0.0f;
}

// ---------------------------------------------------------------------------
// Prefix pooling + h0 = tanh(pooled@Wp2h + bp2h).  grid=BATCH, 256 threads.
// Writes h0 directly into g_h.
// ---------------------------------------------------------------------------
__global__ void pool_kernel(const float* __restrict__ Wscore,
                            const float* __restrict__ Wp2h,
                            const float* __restrict__ bp2h)
{
    int b = blockIdx.x;
    const float* feat = g_feat + (size_t)b * SEQ * DPROJ;   // prefix = rows [0,512)
    __shared__ float wsc[512];
    __shared__ float sc[512];
    __shared__ float pooled[512];
    __shared__ float red[256];
    int tid = threadIdx.x;

    for (int i = tid; i < 512; i += 256) wsc[i] = Wscore[i];
    __syncthreads();

    int w = tid >> 5, l = tid & 31;
    for (int u = w; u < ASSIST; u += 8) {
        float s = 0.0f;
        for (int p = l; p < DPROJ; p += 32)
            s = fmaf(feat[(size_t)u * DPROJ + p], wsc[p], s);
#pragma unroll
        for (int o = 16; o; o >>= 1) s += __shfl_xor_sync(0xffffffffu, s, o);
        if (l == 0) sc[u] = s;
    }
    __syncthreads();

    float m = fmaxf(sc[tid], sc[tid + 256]);
    red[tid] = m; __syncthreads();
    for (int s = 128; s; s >>= 1) { if (tid < s) red[tid] = fmaxf(red[tid], red[tid + s]); __syncthreads(); }
    m = red[0]; __syncthreads();

    float e0 = expf(sc[tid] - m), e1 = expf(sc[tid + 256] - m);
    red[tid] = e0 + e1; __syncthreads();
    for (int s = 128; s; s >>= 1) { if (tid < s) red[tid] += red[tid + s]; __syncthreads(); }
    float inv = 1.0f / red[0];
    __syncthreads();
    sc[tid] = e0 * inv; sc[tid + 256] = e1 * inv;
    __syncthreads();

    for (int p = tid; p < DPROJ; p += 256) {
        float acc = 0.0f;
        for (int u = 0; u < ASSIST; u++)
            acc = fmaf(sc[u], feat[(size_t)u * DPROJ + p], acc);
        pooled[p] = acc;
    }
    __syncthreads();

    for (int c = tid; c < DMEM; c += 256) {
        float acc = bp2h[c];
        for (int k = 0; k < DPROJ; k++)
            acc = fmaf(pooled[k], Wp2h[(size_t)k * DMEM + c], acc);
        g_h[b * DMEM + c] = tanhf(acc);
    }
}

// ---------------------------------------------------------------------------
// init output with bmem (d_out is poisoned before timing)
// ---------------------------------------------------------------------------
__global__ void init_out_kernel(float* __restrict__ out, const float* __restrict__ bmem)
{
    int i = blockIdx.x * blockDim.x + threadIdx.x;
    if (i < BATCH * RUN) out[i] = bmem[0];
}

// ---------------------------------------------------------------------------
// Sequential GRU-style scan. Persistent kernel, 32 blocks x 256 threads.
// Block owns 16 columns of the 512-wide state across Uz/Ur/Uh; each thread
// holds a 32-long k-slice of those columns in REGISTERS (U is step-invariant).
// h / r*h are exchanged through global memory with L1-bypass loads (__ldcg)
// and a sense-reversal grid barrier (2 per step; 3072 total, even -> state
// returns to 0 for the next graph replay).
// ---------------------------------------------------------------------------
#define SCAN_BLOCKS 32
#define NC 16            // columns per block
#define HS 520           // padded row stride for h/rh smem (bank spread)

__device__ __forceinline__ void grid_bar(unsigned* lsense)
{
    __syncthreads();
    if (threadIdx.x == 0) {
        unsigned ns = (*lsense) ^ 1u;
        *lsense = ns;
        unsigned prev = atomicAdd(&g_bar_count, 1u);
        if (prev == SCAN_BLOCKS - 1u) {
            atomicExch(&g_bar_count, 0u);
            __threadfence();
            g_bar_sense = ns;
        } else {
            while (g_bar_sense != ns) { }
        }
    }
    __syncthreads();
}

__global__ void __launch_bounds__(256, 1) scan_kernel(
    const float* __restrict__ Uz, const float* __restrict__ Ur,
    const float* __restrict__ Uh, const float* __restrict__ Wmem,
    float* __restrict__ out)
{
    __shared__ float h_s[BATCH * HS];
    __shared__ float rh_s[BATCH * HS];
    __shared__ float part[256 * 9];
    __shared__ float z_s[NC][BATCH];
    __shared__ float wmem_s[NC];
    __shared__ float logacc[BATCH];

    int tid = threadIdx.x;
    int c   = tid & 15;          // local col
    int seg = tid >> 4;          // 0..15 k-segment
    int cglob = blockIdx.x * NC + c;
    int kbase = seg * 32;

    // register-resident U slices (step-invariant)
    float uz[32], ur[32], uh[32];
#pragma unroll
    for (int i = 0; i < 32; i++) {
        uz[i] = Uz[(size_t)(kbase + i) * DMEM + cglob];
        ur[i] = Ur[(size_t)(kbase + i) * DMEM + cglob];
        uh[i] = Uh[(size_t)(kbase + i) * DMEM + cglob];
    }
    if (seg == 0) wmem_s[c] = Wmem[cglob];

    // initial h (h0 from pool_kernel; previous kernel so L1 is cold -> safe)
    {
        int idx = tid * 8;
#pragma unroll
        for (int j = 0; j < 8; j++) {
            int ii = idx + j;
            h_s[(ii >> 9) * HS + (ii & 511)] = __ldcg(&g_h[ii]);
        }
    }
    unsigned lsense = 0;
    __syncthreads();

    const float dtc = 1.0f / 1535.0f;

    for (int t = 0; t < RUN; t++) {
        float dtv = (t == 0) ? 0.0f : dtc;
        if (tid < BATCH) logacc[tid] = 0.0f;

        // ---- prefetch this step's precomputed inputs (G = x@W + b) ----
        float gA = 0.0f, gH = 0.0f;
        if (tid < 128) {
            int mat = tid >> 6, cc = (tid >> 2) & 15, b = tid & 3;
            const float* P = mat ? g_Gr : g_Gz;
            gA = __ldg(&P[((size_t)(b * RUN + t)) * DMEM + blockIdx.x * NC + cc]);
        }
        if (tid < 64) {
            int cc = tid >> 2, b = tid & 3;
            gH = __ldg(&g_Gh[((size_t)(b * RUN + t)) * DMEM + blockIdx.x * NC + cc]);
        }

        // ---- phase A: partial dots for z and r ----
        float pz[4] = {0, 0, 0, 0}, pr[4] = {0, 0, 0, 0};
#pragma unroll
        for (int i = 0; i < 32; i++) {
            float a = uz[i], bb = ur[i];
#pragma unroll
            for (int b = 0; b < 4; b++) {
                float hv = h_s[b * HS + kbase + i];
                pz[b] = fmaf(hv, a, pz[b]);
                pr[b] = fmaf(hv, bb, pr[b]);
            }
        }
#pragma unroll
        for (int b = 0; b < 4; b++) {
            part[tid * 9 + b]     = pz[b];
            part[tid * 9 + 4 + b] = pr[b];
        }
        __syncthreads();

        if (tid < 128) {
            int mat = tid >> 6, cc = (tid >> 2) & 15, b = tid & 3;
            float s = 0.0f;
#pragma unroll
            for (int sg = 0; sg < 16; sg++)
                s += part[(cc + (sg << 4)) * 9 + mat * 4 + b];
            float v = gA + s;
            float sig = 1.0f / (1.0f + expf(-v));
            if (mat == 0) {
                z_s[cc][b] = sig;
            } else {
                int cg = blockIdx.x * NC + cc;
                g_rh[b * DMEM + cg] = sig * h_s[b * HS + cg];
            }
        }
        __threadfence();
        grid_bar(&lsense);

        // ---- gather full r*h (L1-bypass: written by other SMs) ----
        {
            int idx = tid * 8;
#pragma unroll
            for (int j = 0; j < 8; j++) {
                int ii = idx + j;
                rh_s[(ii >> 9) * HS + (ii & 511)] = __ldcg(&g_rh[ii]);
            }
        }
        __syncthreads();

        // ---- phase B: candidate, state update, logit ----
        float ph[4] = {0, 0, 0, 0};
#pragma unroll
        for (int i = 0; i < 32; i++) {
            float u = uh[i];
#pragma unroll
            for (int b = 0; b < 4; b++)
                ph[b] = fmaf(rh_s[b * HS + kbase + i], u, ph[b]);
        }
#pragma unroll
        for (int b = 0; b < 4; b++) part[tid * 9 + b] = ph[b];
        __syncthreads();

        if (tid < 64) {
            int cc = tid >> 2, b = tid & 3;
            float s = 0.0f;
#pragma unroll
            for (int sg = 0; sg < 16; sg++)
                s += part[(cc + (sg << 4)) * 9 + b];
            int cg = blockIdx.x * NC + cc;
            float hh   = tanhf(gH + s);
            float hold = h_s[b * HS + cg];
            float zv   = z_s[cc][b];
            float hnew = hold + zv * (hh - hold);
            float hout = hnew + dtv * (hnew - hold);
            g_h[b * DMEM + cg] = hout;
            atomicAdd(&logacc[b], hout * wmem_s[cc]);
        }
        __syncthreads();
        if (tid < BATCH) atomicAdd(&out[tid * RUN + t], logacc[tid]);
        __threadfence();
        grid_bar(&lsense);

        // ---- reload full h for next step ----
        {
            int idx = tid * 8;
#pragma unroll
            for (int j = 0; j < 8; j++) {
                int ii = idx + j;
                h_s[(ii >> 9) * HS + (ii & 511)] = __ldcg(&g_h[ii]);
            }
        }
        __syncthreads();
    }
}

// ---------------------------------------------------------------------------
// Host: launch pipeline (graph-capturable, no allocs/syncs)
// ---------------------------------------------------------------------------
extern "C" void kernel_launch(void* const* d_in, const int* in_sizes, int n_in,
                              void* d_out, int out_size)
{
    const float* x      = (const float*)d_in[0];
    const float* Wq     = (const float*)d_in[1];
    const float* bq     = (const float*)d_in[2];
    const float* Wk     = (const float*)d_in[3];
    const float* bk     = (const float*)d_in[4];
    const float* Wv     = (const float*)d_in[5];
    const float* bv     = (const float*)d_in[6];
    const float* Wz     = (const float*)d_in[7];
    const float* Uz     = (const float*)d_in[8];
    const float* bz     = (const float*)d_in[9];
    const float* Wr     = (const float*)d_in[10];
    const float* Ur     = (const float*)d_in[11];
    const float* br     = (const float*)d_in[12];
    const float* Wh     = (const float*)d_in[13];
    const float* Uh     = (const float*)d_in[14];
    const float* bh     = (const float*)d_in[15];
    const float* Wmem   = (const float*)d_in[16];
    const float* bmem   = (const float*)d_in[17];
    const float* Wp2h   = (const float*)d_in[18];
    const float* bp2h   = (const float*)d_in[19];
    const float* Wscore = (const float*)d_in[20];
    (void)in_sizes; (void)n_in;
    float* out = (float*)d_out;

    float *pQ, *pK, *pV, *pS, *pF, *pGz, *pGr, *pGh;
    cudaGetSymbolAddress((void**)&pQ,  g_Q);
    cudaGetSymbolAddress((void**)&pK,  g_K);
    cudaGetSymbolAddress((void**)&pV,  g_V);
    cudaGetSymbolAddress((void**)&pS,  g_S);
    cudaGetSymbolAddress((void**)&pF,  g_feat);
    cudaGetSymbolAddress((void**)&pGz, g_Gz);
    cudaGetSymbolAddress((void**)&pGr, g_Gr);
    cudaGetSymbolAddress((void**)&pGh, g_Gh);

    dim3 t256(256);

    // ---- QKV projections: [8192,4096] x [4096,512] ----
    {
        dim3 g(DPROJ / 64, ROWS / 128, 1);
        sgemm_kernel<<<g, t256>>>(x, Wq, bq, pQ, ROWS, DPROJ, DIN, 0, 0, 0, 0, 0);
        sgemm_kernel<<<g, t256>>>(x, Wk, bk, pK, ROWS, DPROJ, DIN, 0, 0, 0, 0, 0);
        sgemm_kernel<<<g, t256>>>(x, Wv, bv, pV, ROWS, DPROJ, DIN, 0, 0, 0, 0, 0);
    }

    // ---- scores = Q K^T (causal tile skip), per batch ----
    {
        dim3 g(SEQ / 64, SEQ / 128, BATCH);
        sgemm_kernel<<<g, t256>>>(pQ, pK, nullptr, pS, SEQ, SEQ, DPROJ,
                                  (size_t)SEQ * DPROJ, (size_t)SEQ * DPROJ,
                                  (size_t)SEQ * SEQ, 1, 1);
    }

    // ---- causal softmax (in place) ----
    softmax_causal_kernel<<<dim3(SEQ, BATCH), t256>>>();

    // ---- feat = P V ----
    {
        dim3 g(DPROJ / 64, SEQ / 128, BATCH);
        sgemm_kernel<<<g, t256>>>(pS, pV, nullptr, pF, SEQ, DPROJ, SEQ,
                                  (size_t)SEQ * SEQ, (size_t)SEQ * DPROJ,
                                  (size_t)SEQ * DPROJ, 0, 0);
    }

    // ---- prefix pooling -> h0 (into g_h) ----
    pool_kernel<<<BATCH, t256>>>(Wscore, Wp2h, bp2h);

    // ---- precompute scan inputs: G* = feat_assist @ W* + b* ----
    {
        dim3 g(DMEM / 64, RUN / 128, BATCH);
        const float* Aoff = pF + (size_t)ASSIST * DPROJ;  // skip prefix rows
        sgemm_kernel<<<g, t256>>>(Aoff, Wz, bz, pGz, RUN, DMEM, DPROJ,
                                  (size_t)SEQ * DPROJ, 0, (size_t)RUN * DMEM, 0, 0);
        sgemm_kernel<<<g, t256>>>(Aoff, Wr, br, pGr, RUN, DMEM, DPROJ,
                                  (size_t)SEQ * DPROJ, 0, (size_t)RUN * DMEM, 0, 0);
        sgemm_kernel<<<g, t256>>>(Aoff, Wh, bh, pGh, RUN, DMEM, DPROJ,
                                  (size_t)SEQ * DPROJ, 0, (size_t)RUN * DMEM, 0, 0);
    }

    // ---- init output with bmem, then sequential scan ----
    init_out_kernel<<<(BATCH * RUN + 255) / 256, t256>>>(out, bmem);
    scan_kernel<<<SCAN_BLOCKS, t256>>>(Uz, Ur, Uh, Wmem, out);

    (void)out_size;
}

// round 2
// speedup vs baseline: 1.1565x; 1.1565x over previous
#include <cuda_runtime.h>
#include <cuda_bf16.h>
#include <math.h>
#include <stdint.h>

// ---------------------------------------------------------------------------
// Problem constants
// ---------------------------------------------------------------------------
#define BATCH   4
#define SEQ     2048
#define DIN     4096
#define DPROJ   512
#define DMEM    512
#define ASSIST  512
#define RUN     1536
#define ROWS    (BATCH*SEQ)   // 8192

// ---------------------------------------------------------------------------
// Device scratch
// ---------------------------------------------------------------------------
__device__ float g_Q[(size_t)ROWS*DPROJ];
__device__ float g_K[(size_t)ROWS*DPROJ];
__device__ float g_V[(size_t)ROWS*DPROJ];
__device__ float g_S[(size_t)BATCH*SEQ*SEQ];
__device__ float g_feat[(size_t)ROWS*DPROJ];
__device__ float g_Gz[(size_t)BATCH*RUN*DMEM];
__device__ float g_Gr[(size_t)BATCH*RUN*DMEM];
__device__ float g_Gh[(size_t)BATCH*RUN*DMEM];
__device__ float g_h[BATCH*DMEM];
__device__ float g_rh[BATCH*DMEM];
__device__ unsigned g_bar_count = 0;
__device__ volatile unsigned g_bar_sense = 0;

// ---------------------------------------------------------------------------
// SGEMM: C[M,N] = A[M,K] * op(B) (+bias). 128x128x16 tiles, 8x8 microtile,
// double-buffered smem (1 sync / K-tile).
//   transB=0: B[K,N].  transB=1: B[N,K] (C = A*B^T)
//   mode: 0 = plain; 1 = causal tile skip (scores); 2 = K-limit (PV, P lower-tri)
// Requires M%128==0, N%128==0, K%16==0 (true for all call sites).
// ---------------------------------------------------------------------------
__global__ void __launch_bounds__(256, 2) sgemm128(
    const float* __restrict__ A, const float* __restrict__ B,
    const float* __restrict__ bias, float* __restrict__ C,
    int M, int N, int K,
    size_t sA, size_t sB, size_t sC,
    int transB, int mode)
{
    constexpr int BM = 128, BN = 128, BK = 16, PAD = 4;
    __shared__ float As[2][BK][BM + PAD];
    __shared__ float Bs[2][BK][BN + PAD];

    int bx = blockIdx.x, by = blockIdx.y, bz = blockIdx.z;
    int rowBase = by * BM, colBase = bx * BN;
    if (mode == 1 && rowBase + BM - 1 < colBase) return;   // fully masked tile
    int Kend = K;
    if (mode == 2) Kend = (rowBase + BM < K) ? rowBase + BM : K;

    const float* Ab = A + sA * (size_t)bz;
    const float* Bb = B + sB * (size_t)bz;
    float*       Cb = C + sC * (size_t)bz;

    int tid = threadIdx.x;
    int ty = tid >> 4, tx = tid & 15;
    int row0 = ty * 8, col0 = tx * 8;

    // A loader: 128 rows x 16 k; thread -> row=tid/2, k-offset=(tid&1)*8
    int arow = tid >> 1, akof = (tid & 1) * 8;
    const float* aptr = Ab + (size_t)(rowBase + arow) * K + akof;

    // B loaders
    int bkr = tid >> 4, bnc = (tid & 15) * 8;   // !transB: Bs[bkr][bnc..+7]
    int bnr = tid >> 1, bkof = (tid & 1) * 8;   //  transB: Bs[bkof+j][bnr]
    const float* bptr = transB
        ? Bb + (size_t)(colBase + bnr) * K + bkof
        : Bb + (size_t)bkr * N + colBase + bnc;

    float acc[8][8];
#pragma unroll
    for (int i = 0; i < 8; i++)
#pragma unroll
        for (int j = 0; j < 8; j++) acc[i][j] = 0.0f;

    int nTiles = Kend / BK;

    // preload tile 0 into buffer 0
    {
        float4 a0 = *(const float4*)(aptr);
        float4 a1 = *(const float4*)(aptr + 4);
        As[0][akof + 0][arow] = a0.x; As[0][akof + 1][arow] = a0.y;
        As[0][akof + 2][arow] = a0.z; As[0][akof + 3][arow] = a0.w;
        As[0][akof + 4][arow] = a1.x; As[0][akof + 5][arow] = a1.y;
        As[0][akof + 6][arow] = a1.z; As[0][akof + 7][arow] = a1.w;
        float4 b0 = *(const float4*)(bptr);
        float4 b1 = *(const float4*)(bptr + 4);
        if (!transB) {
            *(float4*)&Bs[0][bkr][bnc]     = b0;
            *(float4*)&Bs[0][bkr][bnc + 4] = b1;
        } else {
            Bs[0][bkof + 0][bnr] = b0.x; Bs[0][bkof + 1][bnr] = b0.y;
            Bs[0][bkof + 2][bnr] = b0.z; Bs[0][bkof + 3][bnr] = b0.w;
            Bs[0][bkof + 4][bnr] = b1.x; Bs[0][bkof + 5][bnr] = b1.y;
            Bs[0][bkof + 6][bnr] = b1.z; Bs[0][bkof + 7][bnr] = b1.w;
        }
    }
    __syncthreads();

    int buf = 0;
    for (int t0 = 0; t0 < nTiles; t0++) {
        float4 na0, na1, nb0, nb1;
        bool nxt = (t0 + 1 < nTiles);
        if (nxt) {
            const float* ap = aptr + (t0 + 1) * BK;
            na0 = *(const float4*)(ap);
            na1 = *(const float4*)(ap + 4);
            const float* bp = transB ? bptr + (t0 + 1) * BK
                                     : bptr + (size_t)(t0 + 1) * BK * N;
            nb0 = *(const float4*)(bp);
            nb1 = *(const float4*)(bp + 4);
        }

#pragma unroll
        for (int kk = 0; kk < BK; kk++) {
            float4 a0 = *(const float4*)&As[buf][kk][row0];
            float4 a1 = *(const float4*)&As[buf][kk][row0 + 4];
            float4 b0 = *(const float4*)&Bs[buf][kk][col0];
            float4 b1 = *(const float4*)&Bs[buf][kk][col0 + 4];
            float a[8] = {a0.x, a0.y, a0.z, a0.w, a1.x, a1.y, a1.z, a1.w};
            float b[8] = {b0.x, b0.y, b0.z, b0.w, b1.x, b1.y, b1.z, b1.w};
#pragma unroll
            for (int i = 0; i < 8; i++)
#pragma unroll
                for (int j = 0; j < 8; j++)
                    acc[i][j] = fmaf(a[i], b[j], acc[i][j]);
        }

        if (nxt) {
            int nb = buf ^ 1;
            As[nb][akof + 0][arow] = na0.x; As[nb][akof + 1][arow] = na0.y;
            As[nb][akof + 2][arow] = na0.z; As[nb][akof + 3][arow] = na0.w;
            As[nb][akof + 4][arow] = na1.x; As[nb][akof + 5][arow] = na1.y;
            As[nb][akof + 6][arow] = na1.z; As[nb][akof + 7][arow] = na1.w;
            if (!transB) {
                *(float4*)&Bs[nb][bkr][bnc]     = nb0;
                *(float4*)&Bs[nb][bkr][bnc + 4] = nb1;
            } else {
                Bs[nb][bkof + 0][bnr] = nb0.x; Bs[nb][bkof + 1][bnr] = nb0.y;
                Bs[nb][bkof + 2][bnr] = nb0.z; Bs[nb][bkof + 3][bnr] = nb0.w;
                Bs[nb][bkof + 4][bnr] = nb1.x; Bs[nb][bkof + 5][bnr] = nb1.y;
                Bs[nb][bkof + 6][bnr] = nb1.z; Bs[nb][bkof + 7][bnr] = nb1.w;
            }
        }
        __syncthreads();
        buf ^= 1;
    }

    float4 bv0 = make_float4(0.f, 0.f, 0.f, 0.f);
    float4 bv1 = bv0;
    if (bias) {
        bv0 = *(const float4*)(bias + colBase + col0);
        bv1 = *(const float4*)(bias + colBase + col0 + 4);
    }
#pragma unroll
    for (int i = 0; i < 8; i++) {
        size_t row = (size_t)(rowBase + row0 + i);
        float4 o0 = make_float4(acc[i][0] + bv0.x, acc[i][1] + bv0.y,
                                acc[i][2] + bv0.z, acc[i][3] + bv0.w);
        float4 o1 = make_float4(acc[i][4] + bv1.x, acc[i][5] + bv1.y,
                                acc[i][6] + bv1.z, acc[i][7] + bv1.w);
        *(float4*)(Cb + row * N + colBase + col0)     = o0;
        *(float4*)(Cb + row * N + colBase + col0 + 4) = o1;
    }
}

// ---------------------------------------------------------------------------
// Causal row softmax, in place. exp values cached in smem (single exp pass).
// ---------------------------------------------------------------------------
__global__ void softmax_causal_kernel()
{
    int r = blockIdx.x, b = blockIdx.y;
    float* row = g_S + ((size_t)b * SEQ + r) * SEQ;
    int len = r + 1;
    int tid = threadIdx.x;
    __shared__ float buf[SEQ];
    __shared__ float red[256];
    const float inv = rsqrtf(512.0f);

    float m = -3.4e38f;
    for (int i = tid; i < len; i += 256) m = fmaxf(m, row[i]);
    red[tid] = m; __syncthreads();
    for (int s = 128; s; s >>= 1) { if (tid < s) red[tid] = fmaxf(red[tid], red[tid + s]); __syncthreads(); }
    m = red[0] * inv;
    __syncthreads();

    float ssum = 0.0f;
    for (int i = tid; i < len; i += 256) {
        float e = __expf(row[i] * inv - m);
        buf[i] = e;
        ssum += e;
    }
    red[tid] = ssum; __syncthreads();
    for (int s = 128; s; s >>= 1) { if (tid < s) red[tid] += red[tid + s]; __syncthreads(); }
    float denom = 1.0f / red[0];
    __syncthreads();

    for (int i = tid; i < SEQ; i += 256)
        row[i] = (i < len) ? buf[i] * denom : 0.0f;
}

// ---------------------------------------------------------------------------
// Prefix pooling + h0 = tanh(pooled@Wp2h + bp2h).  grid=BATCH.
// ---------------------------------------------------------------------------
__global__ void pool_kernel(const float* __restrict__ Wscore,
                            const float* __restrict__ Wp2h,
                            const float* __restrict__ bp2h)
{
    int b = blockIdx.x;
    const float* feat = g_feat + (size_t)b * SEQ * DPROJ;
    __shared__ float wsc[512];
    __shared__ float sc[512];
    __shared__ float pooled[512];
    __shared__ float red[256];
    int tid = threadIdx.x;

    for (int i = tid; i < 512; i += 256) wsc[i] = Wscore[i];
    __syncthreads();

    int w = tid >> 5, l = tid & 31;
    for (int u = w; u < ASSIST; u += 8) {
        float s = 0.0f;
        for (int p = l; p < DPROJ; p += 32)
            s = fmaf(feat[(size_t)u * DPROJ + p], wsc[p], s);
#pragma unroll
        for (int o = 16; o; o >>= 1) s += __shfl_xor_sync(0xffffffffu, s, o);
        if (l == 0) sc[u] = s;
    }
    __syncthreads();

    float m = fmaxf(sc[tid], sc[tid + 256]);
    red[tid] = m; __syncthreads();
    for (int s = 128; s; s >>= 1) { if (tid < s) red[tid] = fmaxf(red[tid], red[tid + s]); __syncthreads(); }
    m = red[0]; __syncthreads();

    float e0 = expf(sc[tid] - m), e1 = expf(sc[tid + 256] - m);
    red[tid] = e0 + e1; __syncthreads();
    for (int s = 128; s; s >>= 1) { if (tid < s) red[tid] += red[tid + s]; __syncthreads(); }
    float inv = 1.0f / red[0];
    __syncthreads();
    sc[tid] = e0 * inv; sc[tid + 256] = e1 * inv;
    __syncthreads();

    for (int p = tid; p < DPROJ; p += 256) {
        float acc = 0.0f;
        for (int u = 0; u < ASSIST; u++)
            acc = fmaf(sc[u], feat[(size_t)u * DPROJ + p], acc);
        pooled[p] = acc;
    }
    __syncthreads();

    for (int c = tid; c < DMEM; c += 256) {
        float acc = bp2h[c];
        for (int k = 0; k < DPROJ; k++)
            acc = fmaf(pooled[k], Wp2h[(size_t)k * DMEM + c], acc);
        g_h[b * DMEM + c] = tanhf(acc);
    }
}

__global__ void init_out_kernel(float* __restrict__ out, const float* __restrict__ bmem)
{
    int i = blockIdx.x * blockDim.x + threadIdx.x;
    if (i < BATCH * RUN) out[i] = bmem[0];
}

// ---------------------------------------------------------------------------
// Sequential GRU-style scan. 64 persistent blocks x 256 threads; each block
// owns 8 state columns. U slices register-resident. 2 grid barriers / step.
// ---------------------------------------------------------------------------
#define SCAN_BLOCKS 64
#define NC 8
#define HS 520

__device__ __forceinline__ void grid_bar(unsigned* lsense)
{
    __syncthreads();
    if (threadIdx.x == 0) {
        unsigned ns = (*lsense) ^ 1u;
        *lsense = ns;
        unsigned prev = atomicAdd(&g_bar_count, 1u);
        if (prev == SCAN_BLOCKS - 1u) {
            atomicExch(&g_bar_count, 0u);
            __threadfence();
            g_bar_sense = ns;
        } else {
            while (g_bar_sense != ns) { }
        }
    }
    __syncthreads();
}

__global__ void __launch_bounds__(256, 1) scan_kernel(
    const float* __restrict__ Uz, const float* __restrict__ Ur,
    const float* __restrict__ Uh, const float* __restrict__ Wmem,
    float* __restrict__ out)
{
    __shared__ float h_s[BATCH * HS];
    __shared__ float rh_s[BATCH * HS];
    __shared__ float part[256 * 9];
    __shared__ float z_s[NC * BATCH];
    __shared__ float wmem_s[NC];

    int tid = threadIdx.x;
    int c   = tid & 7;           // local col 0..7
    int seg = tid >> 3;          // 0..31, k-segment of 16
    int cglob = blockIdx.x * NC + c;
    int kbase = seg * 16;

    float uz[16], ur[16], uh[16];
#pragma unroll
    for (int i = 0; i < 16; i++) {
        uz[i] = Uz[(size_t)(kbase + i) * DMEM + cglob];
        ur[i] = Ur[(size_t)(kbase + i) * DMEM + cglob];
        uh[i] = Uh[(size_t)(kbase + i) * DMEM + cglob];
    }
    if (tid < NC) wmem_s[tid] = Wmem[blockIdx.x * NC + tid];

    {
        int idx = tid * 8;
#pragma unroll
        for (int j = 0; j < 8; j++) {
            int ii = idx + j;
            h_s[(ii >> 9) * HS + (ii & 511)] = __ldcg(&g_h[ii]);
        }
    }
    unsigned lsense = 0;
    __syncthreads();

    const float dtc = 1.0f / 1535.0f;

    for (int t = 0; t < RUN; t++) {
        float dtv = (t == 0) ? 0.0f : dtc;

        // prefetch this step's precomputed x@W+b terms
        float gA = 0.0f, gH = 0.0f;
        if (tid < 64) {
            int mat = tid >> 5, idx = tid & 31, cc = idx >> 2, b = idx & 3;
            const float* P = mat ? g_Gr : g_Gz;
            gA = __ldg(&P[((size_t)(b * RUN + t)) * DMEM + blockIdx.x * NC + cc]);
        }
        if (tid < 32) {
            int cc = tid >> 2, b = tid & 3;
            gH = __ldg(&g_Gh[((size_t)(b * RUN + t)) * DMEM + blockIdx.x * NC + cc]);
        }

        // phase A: partial dots for z and r
        float pz[4] = {0, 0, 0, 0}, pr[4] = {0, 0, 0, 0};
#pragma unroll
        for (int i = 0; i < 16; i++) {
            float a = uz[i], rr = ur[i];
#pragma unroll
            for (int b = 0; b < 4; b++) {
                float hv = h_s[b * HS + kbase + i];
                pz[b] = fmaf(hv, a, pz[b]);
                pr[b] = fmaf(hv, rr, pr[b]);
            }
        }
#pragma unroll
        for (int b = 0; b < 4; b++) {
            part[tid * 9 + b]     = pz[b];
            part[tid * 9 + 4 + b] = pr[b];
        }
        __syncthreads();

        if (tid < 64) {
            int mat = tid >> 5, idx = tid & 31, cc = idx >> 2, b = idx & 3;
            float s = 0.0f;
#pragma unroll
            for (int sg = 0; sg < 32; sg++)
                s += part[(sg * 8 + cc) * 9 + mat * 4 + b];
            float v = gA + s;
            float sig = 1.0f / (1.0f + expf(-v));
            if (mat == 0) {
                z_s[cc * 4 + b] = sig;
            } else {
                int cg = blockIdx.x * NC + cc;
                g_rh[b * DMEM + cg] = sig * h_s[b * HS + cg];
            }
        }
        __threadfence();
        grid_bar(&lsense);

        // gather full r*h (written by other SMs; bypass L1)
        {
            int idx = tid * 8;
#pragma unroll
            for (int j = 0; j < 8; j++) {
                int ii = idx + j;
                rh_s[(ii >> 9) * HS + (ii & 511)] = __ldcg(&g_rh[ii]);
            }
        }
        __syncthreads();

        // phase B: candidate, state update, logit
        float ph[4] = {0, 0, 0, 0};
#pragma unroll
        for (int i = 0; i < 16; i++) {
            float u = uh[i];
#pragma unroll
            for (int b = 0; b < 4; b++)
                ph[b] = fmaf(rh_s[b * HS + kbase + i], u, ph[b]);
        }
#pragma unroll
        for (int b = 0; b < 4; b++) part[tid * 9 + b] = ph[b];
        __syncthreads();

        if (tid < 32) {                       // exactly warp 0
            int cc = tid >> 2, b = tid & 3;
            float s = 0.0f;
#pragma unroll
            for (int sg = 0; sg < 32; sg++)
                s += part[(sg * 8 + cc) * 9 + b];
            int cg = blockIdx.x * NC + cc;
            float hh   = tanhf(gH + s);
            float hold = h_s[b * HS + cg];
            float zv   = z_s[cc * 4 + b];
            float hnew = hold + zv * (hh - hold);
            float hout = hnew + dtv * (hnew - hold);
            g_h[b * DMEM + cg] = hout;
            // warp-reduce logit over cc (stride-4 lanes), lane layout cc*4+b
            float lv = hout * wmem_s[cc];
            lv += __shfl_xor_sync(0xffffffffu, lv, 4);
            lv += __shfl_xor_sync(0xffffffffu, lv, 8);
            lv += __shfl_xor_sync(0xffffffffu, lv, 16);
            if (tid < 4) atomicAdd(&out[tid * RUN + t], lv);
        }
        __threadfence();
        grid_bar(&lsense);

        // reload full h for next step
        {
            int idx = tid * 8;
#pragma unroll
            for (int j = 0; j < 8; j++) {
                int ii = idx + j;
                h_s[(ii >> 9) * HS + (ii & 511)] = __ldcg(&g_h[ii]);
            }
        }
        __syncthreads();
    }
}

// ---------------------------------------------------------------------------
// Host
// ---------------------------------------------------------------------------
extern "C" void kernel_launch(void* const* d_in, const int* in_sizes, int n_in,
                              void* d_out, int out_size)
{
    const float* x      = (const float*)d_in[0];
    const float* Wq     = (const float*)d_in[1];
    const float* bq     = (const float*)d_in[2];
    const float* Wk     = (const float*)d_in[3];
    const float* bk     = (const float*)d_in[4];
    const float* Wv     = (const float*)d_in[5];
    const float* bv     = (const float*)d_in[6];
    const float* Wz     = (const float*)d_in[7];
    const float* Uz     = (const float*)d_in[8];
    const float* bz     = (const float*)d_in[9];
    const float* Wr     = (const float*)d_in[10];
    const float* Ur     = (const float*)d_in[11];
    const float* br     = (const float*)d_in[12];
    const float* Wh     = (const float*)d_in[13];
    const float* Uh     = (const float*)d_in[14];
    const float* bh     = (const float*)d_in[15];
    const float* Wmem   = (const float*)d_in[16];
    const float* bmem   = (const float*)d_in[17];
    const float* Wp2h   = (const float*)d_in[18];
    const float* bp2h   = (const float*)d_in[19];
    const float* Wscore = (const float*)d_in[20];
    (void)in_sizes; (void)n_in;
    float* out = (float*)d_out;

    float *pQ, *pK, *pV, *pS, *pF, *pGz, *pGr, *pGh;
    cudaGetSymbolAddress((void**)&pQ,  g_Q);
    cudaGetSymbolAddress((void**)&pK,  g_K);
    cudaGetSymbolAddress((void**)&pV,  g_V);
    cudaGetSymbolAddress((void**)&pS,  g_S);
    cudaGetSymbolAddress((void**)&pF,  g_feat);
    cudaGetSymbolAddress((void**)&pGz, g_Gz);
    cudaGetSymbolAddress((void**)&pGr, g_Gr);
    cudaGetSymbolAddress((void**)&pGh, g_Gh);

    dim3 t256(256);

    // QKV projections: [8192,4096] x [4096,512]
    {
        dim3 g(DPROJ / 128, ROWS / 128, 1);
        sgemm128<<<g, t256>>>(x, Wq, bq, pQ, ROWS, DPROJ, DIN, 0, 0, 0, 0, 0);
        sgemm128<<<g, t256>>>(x, Wk, bk, pK, ROWS, DPROJ, DIN, 0, 0, 0, 0, 0);
        sgemm128<<<g, t256>>>(x, Wv, bv, pV, ROWS, DPROJ, DIN, 0, 0, 0, 0, 0);
    }

    // scores = Q K^T (causal tile skip)
    {
        dim3 g(SEQ / 128, SEQ / 128, BATCH);
        sgemm128<<<g, t256>>>(pQ, pK, nullptr, pS, SEQ, SEQ, DPROJ,
                              (size_t)SEQ * DPROJ, (size_t)SEQ * DPROJ,
                              (size_t)SEQ * SEQ, 1, 1);
    }

    softmax_causal_kernel<<<dim3(SEQ, BATCH), t256>>>();

    // feat = P V  (K limited per row tile: P lower-triangular)
    {
        dim3 g(DPROJ / 128, SEQ / 128, BATCH);
        sgemm128<<<g, t256>>>(pS, pV, nullptr, pF, SEQ, DPROJ, SEQ,
                              (size_t)SEQ * SEQ, (size_t)SEQ * DPROJ,
                              (size_t)SEQ * DPROJ, 0, 2);
    }

    pool_kernel<<<BATCH, t256>>>(Wscore, Wp2h, bp2h);

    // G* = feat_assist @ W* + b*
    {
        dim3 g(DMEM / 128, RUN / 128, BATCH);
        const float* Aoff = pF + (size_t)ASSIST * DPROJ;
        sgemm128<<<g, t256>>>(Aoff, Wz, bz, pGz, RUN, DMEM, DPROJ,
                              (size_t)SEQ * DPROJ, 0, (size_t)RUN * DMEM, 0, 0);
        sgemm128<<<g, t256>>>(Aoff, Wr, br, pGr, RUN, DMEM, DPROJ,
                              (size_t)SEQ * DPROJ, 0, (size_t)RUN * DMEM, 0, 0);
        sgemm128<<<g, t256>>>(Aoff, Wh, bh, pGh, RUN, DMEM, DPROJ,
                              (size_t)SEQ * DPROJ, 0, (size_t)RUN * DMEM, 0, 0);
    }

    init_out_kernel<<<(BATCH * RUN + 255) / 256, t256>>>(out, bmem);
    scan_kernel<<<SCAN_BLOCKS, t256>>>(Uz, Ur, Uh, Wmem, out);

    (void)out_size;
}